// round 11
// baseline (speedup 1.0000x reference)
#include <cuda_runtime.h>
#include <cuda_bf16.h>
#include <math.h>
#include <stdint.h>

#define BB 8
#define SS 1024
#define DD 512
#define HH 8
#define DFFN 2048
#define MROWS (BB*SS)
#define SD (SS*DD)
#define NBH (BB*HH)
typedef __nv_bfloat16 bf;

// ---------------- scratch ---------------------------------------------------
__device__ __align__(128) float g_v  [MROWS*DD];
__device__ __align__(128) float g_res[MROWS*DD];
__device__ __align__(128) float g_x1 [MROWS*DD];
__device__ __align__(128) float g_x2 [MROWS*DD];
__device__ __align__(128) bf g_ah [MROWS*DD];
__device__ __align__(128) bf g_al [MROWS*DD];
__device__ __align__(128) bf g_bh [DFFN*DD];
__device__ __align__(128) bf g_bl [DFFN*DD];
__device__ __align__(128) bf g_qh [NBH*SS*64];
__device__ __align__(128) bf g_ql [NBH*SS*64];
__device__ __align__(128) bf g_kh [NBH*SS*64];
__device__ __align__(128) bf g_kl [NBH*SS*64];
__device__ __align__(128) bf g_vth[NBH*64*SS];
__device__ __align__(128) bf g_vtl[NBH*64*SS];
__device__ __align__(128) bf g_ffh[MROWS*DFFN];
__device__ __align__(128) bf g_ffl[MROWS*DFFN];
__device__ float g_psum[BB*256], g_psumsq[BB*256], g_mr[2*BB];

// ---------------- helpers ---------------------------------------------------
__device__ __forceinline__ uint32_t smem_u32(const void* p) {
    uint32_t a;
    asm("{ .reg .u64 t; cvta.to.shared.u64 t, %1; cvt.u32.u64 %0, t; }" : "=r"(a) : "l"(p));
    return a;
}
__device__ __forceinline__ int swz(int r, int c) {        // 32-elem rows (GEMM)
    return r * 32 + ((((c >> 3) ^ ((r ^ (r >> 1)) & 3)) << 3) | (c & 7));
}
__device__ __forceinline__ int swzK(int r, int c) {       // 64-elem rows
    return r * 64 + ((((c >> 3) ^ (r & 7)) << 3) | (c & 7));
}
__device__ __forceinline__ void cpa16(uint32_t d, const void* s) {
    asm volatile("cp.async.cg.shared.global [%0], [%1], 16;" :: "r"(d), "l"(s));
}
__device__ __forceinline__ void ldsm4(uint32_t* r, uint32_t a) {
    asm volatile("ldmatrix.sync.aligned.m8n8.x4.shared.b16 {%0,%1,%2,%3}, [%4];"
        : "=r"(r[0]), "=r"(r[1]), "=r"(r[2]), "=r"(r[3]) : "r"(a));
}
__device__ __forceinline__ void hmma(float* d, const uint32_t* a, const uint32_t* b) {
    asm volatile("mma.sync.aligned.m16n8k16.row.col.f32.bf16.bf16.f32 "
        "{%0,%1,%2,%3}, {%4,%5,%6,%7}, {%8,%9}, {%0,%1,%2,%3};"
        : "+f"(d[0]), "+f"(d[1]), "+f"(d[2]), "+f"(d[3])
        : "r"(a[0]), "r"(a[1]), "r"(a[2]), "r"(a[3]), "r"(b[0]), "r"(b[1]));
}
__device__ __forceinline__ void split1(float x, bf& h, bf& l) {
    h = __float2bfloat16(x);
    l = __float2bfloat16(x - __bfloat162float(h));
}
__device__ __forceinline__ uint32_t pack2(bf a, bf b) {
    __nv_bfloat162 t; t.x = a; t.y = b;
    return *(uint32_t*)&t;
}

// ---------------- HMMA split-bf16 GEMM (unchanged from R9) ------------------
// EPI: 0 +bias->fp32 ; 1 +bias+resid->fp32 ; 4 +bias->split per-head bf16 ;
//      5 relu(+bias)->split flat
template<int BN, int EPI>
__global__ void __launch_bounds__(256) mma_gemm(
    const bf* __restrict__ Ahp, const bf* __restrict__ Alp,
    const bf* __restrict__ Bhp, const bf* __restrict__ Blp,
    const float* __restrict__ bias, const float* __restrict__ resid,
    float* __restrict__ C, int K, int ldc,
    bf* __restrict__ Oh, bf* __restrict__ Ol)
{
    constexpr int BM = 128;
    constexpr int TN = BN / 16;
    constexpr int AE = BM * 32, BE = BN * 32, OFF_B = 4 * AE;
    extern __shared__ __align__(16) bf sm[];
    const int tid = threadIdx.x, lane = tid & 31, wid = tid >> 5;
    const int wm = wid & 3, wn = wid >> 2;
    const int bm = blockIdx.y * BM, bn = blockIdx.x * BN;
    const bf* gA[2] = { Ahp + (long long)bm * K, Alp + (long long)bm * K };
    const bf* gB[2] = { Bhp + (long long)bn * K, Blp + (long long)bn * K };
    const uint32_t smb = smem_u32(sm);

    float acc[2][TN][4];
#pragma unroll
    for (int i = 0; i < 2; i++)
#pragma unroll
        for (int j = 0; j < TN; j++)
#pragma unroll
            for (int q = 0; q < 4; q++) acc[i][j][q] = 0.f;

    auto prefetch = [&](int kt) {
        const int s = kt & 1;
        const long long kof = (long long)kt * 32;
#pragma unroll
        for (int h = 0; h < 2; h++) {
#pragma unroll
            for (int i = 0; i < 2; i++) {
                int u = tid + i * 256;
                int r = u >> 2, c = (u & 3) << 3;
                cpa16(smb + (uint32_t)(((s*2+h)*AE + swz(r, c)) * 2),
                      gA[h] + (long long)r * K + kof + c);
            }
#pragma unroll
            for (int i = 0; i < BN / 64; i++) {
                int u = tid + i * 256;
                int r = u >> 2, c = (u & 3) << 3;
                cpa16(smb + (uint32_t)((OFF_B + (s*2+h)*BE + swz(r, c)) * 2),
                      gB[h] + (long long)r * K + kof + c);
            }
        }
    };
    auto compute = [&](int s) {
        const uint32_t bA0 = smb + (uint32_t)((s*2    ) * AE * 2);
        const uint32_t bA1 = smb + (uint32_t)((s*2 + 1) * AE * 2);
        const uint32_t bB0 = smb + (uint32_t)((OFF_B + (s*2    ) * BE) * 2);
        const uint32_t bB1 = smb + (uint32_t)((OFF_B + (s*2 + 1) * BE) * 2);
#pragma unroll
        for (int ks = 0; ks < 2; ks++) {
            uint32_t aF[2][2][4], bF[2][TN/2][4];
            const int rA = wm * 32 + (lane & 15);
            const int cA = ks * 16 + (lane >> 4) * 8;
#pragma unroll
            for (int tm = 0; tm < 2; tm++) {
                int off = swz(rA + tm * 16, cA) * 2;
                ldsm4(aF[0][tm], bA0 + off);
                ldsm4(aF[1][tm], bA1 + off);
            }
            const int rB = wn * (BN/2) + ((lane >> 4) & 1) * 8 + (lane & 7);
            const int cB = ks * 16 + ((lane >> 3) & 1) * 8;
#pragma unroll
            for (int p = 0; p < TN/2; p++) {
                int off = swz(rB + p * 16, cB) * 2;
                ldsm4(bF[0][p], bB0 + off);
                ldsm4(bF[1][p], bB1 + off);
            }
#pragma unroll
            for (int tm = 0; tm < 2; tm++)
#pragma unroll
                for (int tn = 0; tn < TN; tn++) {
                    uint32_t* bh_ = &bF[0][tn >> 1][(tn & 1) * 2];
                    uint32_t* bl_ = &bF[1][tn >> 1][(tn & 1) * 2];
                    hmma(acc[tm][tn], aF[0][tm], bh_);
                    hmma(acc[tm][tn], aF[0][tm], bl_);
                    hmma(acc[tm][tn], aF[1][tm], bh_);
                }
        }
    };

    const int NT = K >> 5;
    prefetch(0);
    asm volatile("cp.async.commit_group;");
    for (int kt = 0; kt < NT; kt++) {
        if (kt + 1 < NT) {
            prefetch(kt + 1);
            asm volatile("cp.async.commit_group;");
            asm volatile("cp.async.wait_group 1;");
        } else {
            asm volatile("cp.async.wait_group 0;");
        }
        __syncthreads();
        compute(kt & 1);
        __syncthreads();
    }

#pragma unroll
    for (int tm = 0; tm < 2; tm++)
#pragma unroll
        for (int tn = 0; tn < TN; tn++) {
            const int col = bn + wn * (BN/2) + tn * 8 + (lane & 3) * 2;
            const int row0 = bm + wm * 32 + tm * 16 + (lane >> 2);
            float2 bv = *(const float2*)(bias + col);
#pragma unroll
            for (int hf = 0; hf < 2; hf++) {
                const int row = row0 + hf * 8;
                float v0 = acc[tm][tn][hf*2]     + bv.x;
                float v1 = acc[tm][tn][hf*2 + 1] + bv.y;
                if (EPI == 5) { v0 = fmaxf(v0, 0.f); v1 = fmaxf(v1, 0.f); }
                if (EPI == 1) {
                    float2 rv = *(const float2*)(resid + (long long)row * ldc + col);
                    v0 += rv.x; v1 += rv.y;
                }
                if (EPI <= 1) {
                    float2 o; o.x = v0; o.y = v1;
                    *(float2*)(C + (long long)row * ldc + col) = o;
                } else {
                    bf h0,l0,h1,l1; split1(v0,h0,l0); split1(v1,h1,l1);
                    size_t dst;
                    if (EPI == 4) {
                        int hh = col >> 6, d = col & 63;
                        dst = ((((size_t)(row >> 10)) * 8 + hh) * 1024 + (row & 1023)) * 64 + d;
                    } else {
                        dst = (size_t)row * ldc + col;
                    }
                    *(uint32_t*)(Oh + dst) = pack2(h0, h1);
                    *(uint32_t*)(Ol + dst) = pack2(l0, l1);
                }
            }
        }
}

// ---------------- flash attention v2 (64-key chunks, 2 CTA/SM budget) -------
// smem bytes: QH 0, QL 16K, K bufs @32K (buf*16K, +8K lo), V bufs @64K, mask @96K
#define FQ 0
#define FK 32768
#define FV 65536
#define FM 98304
#define FSMEM 98816

__global__ void __launch_bounds__(256, 2) flash_kernel(
    const bf* __restrict__ Qh, const bf* __restrict__ Ql,
    const bf* __restrict__ Kh, const bf* __restrict__ Kl,
    const bf* __restrict__ Vth, const bf* __restrict__ Vtl,
    const int* __restrict__ mask, bf* __restrict__ Oh, bf* __restrict__ Ol)
{
    extern __shared__ __align__(16) bf fsm[];
    int* sM = (int*)((char*)fsm + FM);
    const int tid = threadIdx.x, lane = tid & 31, w = tid >> 5;
    const int qblk = blockIdx.x * 128, bh = blockIdx.y, b = bh >> 3, h = bh & 7;
    const uint32_t smb = smem_u32(fsm);

    // Q tile (hi/lo) once: 128 rows x 64 elems x 2 halves
#pragma unroll
    for (int i = 0; i < 8; i++) {
        int u = tid + i * 256;
        int hl = u >> 10, u2 = u & 1023, r = u2 >> 3, c = (u2 & 7) << 3;
        cpa16(smb + (uint32_t)(FQ + hl * 16384 + swzK(r, c) * 2),
              (hl ? Ql : Qh) + ((size_t)bh * 1024 + qblk + r) * 64 + c);
    }
    auto pf = [&](int kc) {
        int buf = kc & 1;
#pragma unroll
        for (int i = 0; i < 4; i++) {
            int u = tid + i * 256;
            int hl = u >> 9, u2 = u & 511, r = u2 >> 3, c = (u2 & 7) << 3;
            cpa16(smb + (uint32_t)(FK + buf * 16384 + hl * 8192 + swzK(r, c) * 2),
                  (hl ? Kl : Kh) + ((size_t)bh * 1024 + kc * 64 + r) * 64 + c);
        }
#pragma unroll
        for (int i = 0; i < 4; i++) {
            int u = tid + i * 256;
            int hl = u >> 9, u2 = u & 511, r = u2 >> 3, c = (u2 & 7) << 3;
            cpa16(smb + (uint32_t)(FV + buf * 16384 + hl * 8192 + swzK(r, c) * 2),
                  (hl ? Vtl : Vth) + ((size_t)bh * 64 + r) * 1024 + kc * 64 + c);
        }
        if (tid < 64) sM[buf * 64 + tid] = mask[b * 1024 + kc * 64 + tid];
    };
    pf(0);
    asm volatile("cp.async.commit_group;");

    float acc_o[8][4];
#pragma unroll
    for (int i = 0; i < 8; i++)
#pragma unroll
        for (int q = 0; q < 4; q++) acc_o[i][q] = 0.f;
    float mA = -INFINITY, mB = -INFINITY, lA = 0.f, lB = 0.f;

    for (int kc = 0; kc < 16; kc++) {
        if (kc < 15) {
            pf(kc + 1);
            asm volatile("cp.async.commit_group;");
            asm volatile("cp.async.wait_group 1;");
        } else {
            asm volatile("cp.async.wait_group 0;");
        }
        __syncthreads();
        const int buf = kc & 1;
        const uint32_t kb0 = smb + (uint32_t)(FK + buf * 16384);
        const uint32_t kb1 = kb0 + 8192;
        // ---- S = Q K^T (128x64 per CTA; warp = 16 rows) ----
        float s[8][4];
#pragma unroll
        for (int i = 0; i < 8; i++)
#pragma unroll
            for (int q = 0; q < 4; q++) s[i][q] = 0.f;
#pragma unroll
        for (int ks = 0; ks < 4; ks++) {
            uint32_t aQh[4], aQl[4];
            const int rA = w * 16 + (lane & 15);
            const int cA = ks * 16 + (lane >> 4) * 8;
            {
                int off = swzK(rA, cA) * 2;
                ldsm4(aQh, smb + (uint32_t)(FQ + off));
                ldsm4(aQl, smb + (uint32_t)(FQ + 16384 + off));
            }
            const int cB = ks * 16 + ((lane >> 3) & 1) * 8;
#pragma unroll
            for (int p = 0; p < 4; p++) {
                uint32_t bh_[4], bl_[4];
                int rB = p * 16 + ((lane >> 4) & 1) * 8 + (lane & 7);
                int off = swzK(rB, cB) * 2;
                ldsm4(bh_, kb0 + off);
                ldsm4(bl_, kb1 + off);
#pragma unroll
                for (int hf = 0; hf < 2; hf++) {
                    int tn = p * 2 + hf;
                    hmma(s[tn], aQh, bh_ + hf * 2);
                    hmma(s[tn], aQh, bl_ + hf * 2);
                    hmma(s[tn], aQl, bh_ + hf * 2);
                }
            }
        }
        // ---- masked online softmax (rows r: [0..1]=A, rows r+8: [2..3]=B) --
        const int* mrow = sM + buf * 64;
        float cmA = -INFINITY, cmB = -INFINITY;
#pragma unroll
        for (int tn = 0; tn < 8; tn++) {
            int col = tn * 8 + (lane & 3) * 2;
            bool k0 = mrow[col] != 0, k1 = mrow[col + 1] != 0;
            s[tn][0] = k0 ? s[tn][0] * 0.125f : -1e10f;
            s[tn][2] = k0 ? s[tn][2] * 0.125f : -1e10f;
            s[tn][1] = k1 ? s[tn][1] * 0.125f : -1e10f;
            s[tn][3] = k1 ? s[tn][3] * 0.125f : -1e10f;
            cmA = fmaxf(cmA, fmaxf(s[tn][0], s[tn][1]));
            cmB = fmaxf(cmB, fmaxf(s[tn][2], s[tn][3]));
        }
        cmA = fmaxf(cmA, __shfl_xor_sync(~0u, cmA, 1));
        cmA = fmaxf(cmA, __shfl_xor_sync(~0u, cmA, 2));
        cmB = fmaxf(cmB, __shfl_xor_sync(~0u, cmB, 1));
        cmB = fmaxf(cmB, __shfl_xor_sync(~0u, cmB, 2));
        float mAn = fmaxf(mA, cmA), mBn = fmaxf(mB, cmB);
        float corA = __expf(mA - mAn), corB = __expf(mB - mBn);
        float sumA = 0.f, sumB = 0.f;
#pragma unroll
        for (int tn = 0; tn < 8; tn++) {
            s[tn][0] = __expf(s[tn][0] - mAn); s[tn][1] = __expf(s[tn][1] - mAn);
            s[tn][2] = __expf(s[tn][2] - mBn); s[tn][3] = __expf(s[tn][3] - mBn);
            sumA += s[tn][0] + s[tn][1];
            sumB += s[tn][2] + s[tn][3];
        }
        sumA += __shfl_xor_sync(~0u, sumA, 1); sumA += __shfl_xor_sync(~0u, sumA, 2);
        sumB += __shfl_xor_sync(~0u, sumB, 1); sumB += __shfl_xor_sync(~0u, sumB, 2);
        lA = lA * corA + sumA; lB = lB * corB + sumB;
        mA = mAn; mB = mBn;
#pragma unroll
        for (int tn = 0; tn < 8; tn++) {
            acc_o[tn][0] *= corA; acc_o[tn][1] *= corA;
            acc_o[tn][2] *= corB; acc_o[tn][3] *= corB;
        }
        // ---- O += P V (P fragments retyped from S accumulators) ----
        const uint32_t vb0 = smb + (uint32_t)(FV + buf * 16384);
        const uint32_t vb1 = vb0 + 8192;
#pragma unroll
        for (int ks2 = 0; ks2 < 4; ks2++) {
            float* t0 = s[2 * ks2];
            float* t1 = s[2 * ks2 + 1];
            uint32_t aH[4], aL[4];
#pragma unroll
            for (int j = 0; j < 2; j++) {
                bf ha0,la0,ha1,la1,hb0,lb0,hb1,lb1;
                split1(t0[j*2],   ha0, la0); split1(t0[j*2+1], ha1, la1);
                split1(t1[j*2],   hb0, lb0); split1(t1[j*2+1], hb1, lb1);
                aH[j]   = pack2(ha0, ha1); aL[j]   = pack2(la0, la1);
                aH[j+2] = pack2(hb0, hb1); aL[j+2] = pack2(lb0, lb1);
            }
            const int cB = ks2 * 16 + ((lane >> 3) & 1) * 8;
#pragma unroll
            for (int pn = 0; pn < 4; pn++) {
                uint32_t vh_[4], vl_[4];
                int rB = pn * 16 + ((lane >> 4) & 1) * 8 + (lane & 7);
                int off = swzK(rB, cB) * 2;
                ldsm4(vh_, vb0 + off);
                ldsm4(vl_, vb1 + off);
#pragma unroll
                for (int hf = 0; hf < 2; hf++) {
                    int tn = pn * 2 + hf;
                    hmma(acc_o[tn], aH, vh_ + hf * 2);
                    hmma(acc_o[tn], aH, vl_ + hf * 2);
                    hmma(acc_o[tn], aL, vh_ + hf * 2);
                }
            }
        }
        __syncthreads();
    }
    // ---- write O (split bf16, flat [B*S][512]) ----
    float invA = 1.f / lA, invB = 1.f / lB;
    const int row0 = qblk + w * 16 + (lane >> 2);
#pragma unroll
    for (int tn = 0; tn < 8; tn++) {
        int col = tn * 8 + (lane & 3) * 2;
        size_t f0 = ((size_t)b * 1024 + row0) * 512 + h * 64 + col;
        size_t f1 = f0 + 8 * 512;
        float o0 = acc_o[tn][0] * invA, o1 = acc_o[tn][1] * invA;
        float o2 = acc_o[tn][2] * invB, o3 = acc_o[tn][3] * invB;
        bf h0,l0,h1,l1,h2,l2,h3,l3;
        split1(o0,h0,l0); split1(o1,h1,l1); split1(o2,h2,l2); split1(o3,h3,l3);
        *(uint32_t*)(Oh + f0) = pack2(h0, h1);
        *(uint32_t*)(Ol + f0) = pack2(l0, l1);
        *(uint32_t*)(Oh + f1) = pack2(h2, h3);
        *(uint32_t*)(Ol + f1) = pack2(l2, l3);
    }
}

// ---------------- conversions -----------------------------------------------
__device__ __forceinline__ void st4(bf* oh, bf* ol, size_t o, float a, float b, float c, float d) {
    bf h0,h1,h2,h3,l0,l1,l2,l3;
    split1(a,h0,l0); split1(b,h1,l1); split1(c,h2,l2); split1(d,h3,l3);
    *(uint32_t*)(oh + o)     = pack2(h0, h1);
    *(uint32_t*)(oh + o + 2) = pack2(h2, h3);
    *(uint32_t*)(ol + o)     = pack2(l0, l1);
    *(uint32_t*)(ol + o + 2) = pack2(l2, l3);
}
__global__ void __launch_bounds__(256) split_flat(const float* __restrict__ in, bf* oh, bf* ol) {
    size_t i4 = ((size_t)blockIdx.x * 256 + threadIdx.x) * 4;
    float4 v = *(const float4*)(in + i4);
    st4(oh, ol, i4, v.x, v.y, v.z, v.w);
}
__global__ void __launch_bounds__(256) split_vt(const float* __restrict__ in, bf* oh, bf* ol) {
    __shared__ float t[32][33];
    int s0 = blockIdx.x * 32, d0 = blockIdx.y * 32, bh = blockIdx.z;
    int b = bh >> 3, h = bh & 7;
    int tx = threadIdx.x, ty = threadIdx.y;
#pragma unroll
    for (int j = 0; j < 4; j++)
        t[ty + j*8][tx] = in[((size_t)(b * SS + s0 + ty + j*8)) * 512 + h * 64 + d0 + tx];
    __syncthreads();
#pragma unroll
    for (int j = 0; j < 4; j++) {
        int d = d0 + ty + j*8;
        bf hh, ll; split1(t[tx][ty + j*8], hh, ll);
        size_t o = ((size_t)bh * 64 + d) * SS + s0 + tx;
        oh[o] = hh; ol[o] = ll;
    }
}
__global__ void __launch_bounds__(256) split_whead(const float* __restrict__ in, bf* oh, bf* ol) {
    __shared__ float t[32][33];
    int k0 = blockIdx.x * 32, d0 = blockIdx.y * 32, h = blockIdx.z;
    int tx = threadIdx.x, ty = threadIdx.y;
#pragma unroll
    for (int j = 0; j < 4; j++)
        t[ty + j*8][tx] = in[(size_t)h * 32768 + (size_t)(k0 + ty + j*8) * 64 + d0 + tx];
    __syncthreads();
#pragma unroll
    for (int j = 0; j < 4; j++) {
        int d = d0 + ty + j*8;
        bf hh, ll; split1(t[tx][ty + j*8], hh, ll);
        size_t o = ((size_t)(h * 64 + d)) * 512 + k0 + tx;
        oh[o] = hh; ol[o] = ll;
    }
}

// ---------------- LayerNorm --------------------------------------------------
__global__ void __launch_bounds__(256) ln_partial_kernel(const float* __restrict__ X) {
    int b = blockIdx.x >> 8, c = blockIdx.x & 255, tid = threadIdx.x;
    const float* p = X + (size_t)b * SD + (size_t)c * 2048;
    float s = 0.f, s2 = 0.f;
#pragma unroll
    for (int i = 0; i < 8; i++) { float v = p[tid + i*256]; s += v; s2 += v*v; }
    __shared__ float sh[256], sh2[256];
    sh[tid] = s; sh2[tid] = s2; __syncthreads();
    for (int o = 128; o; o >>= 1) {
        if (tid < o) { sh[tid] += sh[tid+o]; sh2[tid] += sh2[tid+o]; }
        __syncthreads();
    }
    if (tid == 0) { g_psum[blockIdx.x] = sh[0]; g_psumsq[blockIdx.x] = sh2[0]; }
}
__global__ void __launch_bounds__(256) ln_final_kernel() {
    int b = blockIdx.x, tid = threadIdx.x;
    __shared__ float sh[256], sh2[256];
    sh[tid] = g_psum[b*256 + tid]; sh2[tid] = g_psumsq[b*256 + tid];
    __syncthreads();
    for (int o = 128; o; o >>= 1) {
        if (tid < o) { sh[tid] += sh[tid+o]; sh2[tid] += sh2[tid+o]; }
        __syncthreads();
    }
    if (tid == 0) {
        float mean = sh[0] / (float)SD;
        float var = sh2[0] / (float)SD - mean * mean;
        g_mr[2*b] = mean; g_mr[2*b+1] = rsqrtf(var + 1e-6f);
    }
}
__global__ void __launch_bounds__(256) ln_apply_split(
    const float* __restrict__ X, const float* __restrict__ w,
    const float* __restrict__ bb, float* __restrict__ Y, bf* oh, bf* ol)
{
    size_t base = ((size_t)blockIdx.x * 256 + threadIdx.x) * 4;
    int b = (int)(base / SD); size_t sd = base % SD;
    float mean = g_mr[2*b], rstd = g_mr[2*b+1];
    float4 xv = *(const float4*)(X + base);
    float4 wv = *(const float4*)(w + sd);
    float4 bv = *(const float4*)(bb + sd);
    float4 yv;
    yv.x = (xv.x-mean)*rstd*wv.x + bv.x; yv.y = (xv.y-mean)*rstd*wv.y + bv.y;
    yv.z = (xv.z-mean)*rstd*wv.z + bv.z; yv.w = (xv.w-mean)*rstd*wv.w + bv.w;
    *(float4*)(Y + base) = yv;
    st4(oh, ol, base, yv.x, yv.y, yv.z, yv.w);
}

// ---------------- host driver ------------------------------------------------
#define SM128 65536

struct P {
    float *v, *res, *x1, *x2;
    bf *ah,*al,*bh,*bl,*qh,*ql,*kh,*kl,*vth,*vtl,*ffh,*ffl;
};

static void run_ln(const float* X, const float* w, const float* b, float* Y, bf* oh, bf* ol) {
    ln_partial_kernel<<<BB*256, 256>>>(X);
    ln_final_kernel<<<BB, 256>>>();
    ln_apply_split<<<4096, 256>>>(X, w, b, Y, oh, ol);
}

// q input split already in p.ah/p.al on entry
static void mha_stage(P& p, bool kv_from_y, const float* y,
    const float* wq, const float* bq, const float* wk, const float* bk,
    const float* wv, const float* bv, const float* wo, const float* bo,
    const int* mask, const float* resid, float* outres)
{
    dim3 gP(4, 64), gW(16, 2, 8), bW(32, 8), gVT(32, 2, 64), gFA(8, 64);
    split_whead<<<gW, bW>>>(wq, p.bh, p.bl);
    mma_gemm<128,4><<<gP, 256, SM128>>>(p.ah, p.al, p.bh, p.bl, bq, nullptr, nullptr,
        512, 512, p.qh, p.ql);
    if (kv_from_y) split_flat<<<4096, 256>>>(y, p.ah, p.al);
    split_whead<<<gW, bW>>>(wk, p.bh, p.bl);
    mma_gemm<128,4><<<gP, 256, SM128>>>(p.ah, p.al, p.bh, p.bl, bk, nullptr, nullptr,
        512, 512, p.kh, p.kl);
    split_whead<<<gW, bW>>>(wv, p.bh, p.bl);
    mma_gemm<128,0><<<gP, 256, SM128>>>(p.ah, p.al, p.bh, p.bl, bv, nullptr, p.v,
        512, 512, nullptr, nullptr);
    split_vt<<<gVT, bW>>>(p.v, p.vth, p.vtl);

    flash_kernel<<<gFA, 256, FSMEM>>>(p.qh, p.ql, p.kh, p.kl, p.vth, p.vtl, mask, p.ah, p.al);

    split_flat<<<256, 256>>>(wo, p.bh, p.bl);
    mma_gemm<128,1><<<gP, 256, SM128>>>(p.ah, p.al, p.bh, p.bl, bo, resid, outres,
        512, 512, nullptr, nullptr);
}

extern "C" void kernel_launch(void* const* d_in, const int* in_sizes, int n_in,
                              void* d_out, int out_size)
{
#define FP(i) ((const float*)d_in[i])
    const int* src_mask = (const int*)d_in[2];
    const int* trg_mask = (const int*)d_in[3];
    float* out = (float*)d_out;

    cudaFuncSetAttribute(mma_gemm<128,0>, cudaFuncAttributeMaxDynamicSharedMemorySize, SM128);
    cudaFuncSetAttribute(mma_gemm<128,1>, cudaFuncAttributeMaxDynamicSharedMemorySize, SM128);
    cudaFuncSetAttribute(mma_gemm<128,4>, cudaFuncAttributeMaxDynamicSharedMemorySize, SM128);
    cudaFuncSetAttribute(mma_gemm<128,5>, cudaFuncAttributeMaxDynamicSharedMemorySize, SM128);
    cudaFuncSetAttribute(flash_kernel,    cudaFuncAttributeMaxDynamicSharedMemorySize, FSMEM);

    P p;
    cudaGetSymbolAddress((void**)&p.v,   g_v);   cudaGetSymbolAddress((void**)&p.res, g_res);
    cudaGetSymbolAddress((void**)&p.x1,  g_x1);  cudaGetSymbolAddress((void**)&p.x2,  g_x2);
    cudaGetSymbolAddress((void**)&p.ah,  g_ah);  cudaGetSymbolAddress((void**)&p.al,  g_al);
    cudaGetSymbolAddress((void**)&p.bh,  g_bh);  cudaGetSymbolAddress((void**)&p.bl,  g_bl);
    cudaGetSymbolAddress((void**)&p.qh,  g_qh);  cudaGetSymbolAddress((void**)&p.ql,  g_ql);
    cudaGetSymbolAddress((void**)&p.kh,  g_kh);  cudaGetSymbolAddress((void**)&p.kl,  g_kl);
    cudaGetSymbolAddress((void**)&p.vth, g_vth); cudaGetSymbolAddress((void**)&p.vtl, g_vtl);
    cudaGetSymbolAddress((void**)&p.ffh, g_ffh); cudaGetSymbolAddress((void**)&p.ffl, g_ffl);

    // ---- stage 1: self-attention ----
    split_flat<<<4096, 256>>>(FP(0), p.ah, p.al);
    mha_stage(p, false, nullptr, FP(4), FP(5), FP(6), FP(7), FP(8), FP(9), FP(10), FP(11),
              trg_mask, FP(0), p.res);
    run_ln(p.res, FP(24), FP(25), p.x1, p.ah, p.al);

    // ---- stage 2: cross-attention ----
    mha_stage(p, true, FP(1), FP(12), FP(13), FP(14), FP(15), FP(16), FP(17), FP(18), FP(19),
              src_mask, p.x1, p.res);
    run_ln(p.res, FP(26), FP(27), p.x2, p.ah, p.al);

    // ---- stage 3: FFN ----
    split_flat<<<1024, 256>>>(FP(20), p.bh, p.bl);
    mma_gemm<128,5><<<dim3(16, 64), 256, SM128>>>(p.ah, p.al, p.bh, p.bl, FP(21), nullptr,
        nullptr, 512, 2048, p.ffh, p.ffl);
    split_flat<<<1024, 256>>>(FP(22), p.bh, p.bl);
    mma_gemm<128,1><<<dim3(4, 64), 256, SM128>>>(p.ffh, p.ffl, p.bh, p.bl, FP(23), p.x2,
        p.res, 2048, 512, nullptr, nullptr);
    run_ln(p.res, FP(28), FP(29), out, p.ah, p.al);
}

// round 12
// speedup vs baseline: 1.3260x; 1.3260x over previous
#include <cuda_runtime.h>
#include <cuda_bf16.h>
#include <math.h>
#include <stdint.h>

#define BB 8
#define SS 1024
#define DD 512
#define HH 8
#define DFFN 2048
#define MROWS (BB*SS)
#define SD (SS*DD)
#define NBH (BB*HH)
typedef __nv_bfloat16 bf;

// ---------------- scratch ---------------------------------------------------
__device__ __align__(128) float g_v  [MROWS*DD];
__device__ __align__(128) float g_res[MROWS*DD];
__device__ __align__(128) float g_x1 [MROWS*DD];
__device__ __align__(128) float g_x2 [MROWS*DD];
__device__ __align__(128) float g_S  [(size_t)NBH*SS*SS];
__device__ __align__(128) bf g_ah [MROWS*DD];
__device__ __align__(128) bf g_al [MROWS*DD];
__device__ __align__(128) bf g_bh [DFFN*DD];
__device__ __align__(128) bf g_bl [DFFN*DD];
__device__ __align__(128) bf g_qh [NBH*SS*64];
__device__ __align__(128) bf g_ql [NBH*SS*64];
__device__ __align__(128) bf g_kh [NBH*SS*64];
__device__ __align__(128) bf g_kl [NBH*SS*64];
__device__ __align__(128) bf g_vth[NBH*64*SS];
__device__ __align__(128) bf g_vtl[NBH*64*SS];
__device__ __align__(128) bf g_ffh[MROWS*DFFN];
__device__ __align__(128) bf g_ffl[MROWS*DFFN];
__device__ float g_psum[BB*256], g_psumsq[BB*256], g_mr[2*BB];

// ---------------- helpers ---------------------------------------------------
__device__ __forceinline__ uint32_t smem_u32(const void* p) {
    uint32_t a;
    asm("{ .reg .u64 t; cvta.to.shared.u64 t, %1; cvt.u32.u64 %0, t; }" : "=r"(a) : "l"(p));
    return a;
}
__device__ __forceinline__ int swz(int r, int c) {        // 32-elem rows (GEMM)
    return r * 32 + ((((c >> 3) ^ ((r ^ (r >> 1)) & 3)) << 3) | (c & 7));
}
__device__ __forceinline__ int swzK(int r, int c) {       // 64-elem rows
    return r * 64 + ((((c >> 3) ^ (r & 7)) << 3) | (c & 7));
}
__device__ __forceinline__ void cpa16(uint32_t d, const void* s) {
    asm volatile("cp.async.cg.shared.global [%0], [%1], 16;" :: "r"(d), "l"(s));
}
__device__ __forceinline__ void cpa4(uint32_t d, const void* s) {
    asm volatile("cp.async.ca.shared.global [%0], [%1], 4;" :: "r"(d), "l"(s));
}
__device__ __forceinline__ void ldsm4(uint32_t* r, uint32_t a) {
    asm volatile("ldmatrix.sync.aligned.m8n8.x4.shared.b16 {%0,%1,%2,%3}, [%4];"
        : "=r"(r[0]), "=r"(r[1]), "=r"(r[2]), "=r"(r[3]) : "r"(a));
}
__device__ __forceinline__ void hmma(float* d, const uint32_t* a, const uint32_t* b) {
    asm volatile("mma.sync.aligned.m16n8k16.row.col.f32.bf16.bf16.f32 "
        "{%0,%1,%2,%3}, {%4,%5,%6,%7}, {%8,%9}, {%0,%1,%2,%3};"
        : "+f"(d[0]), "+f"(d[1]), "+f"(d[2]), "+f"(d[3])
        : "r"(a[0]), "r"(a[1]), "r"(a[2]), "r"(a[3]), "r"(b[0]), "r"(b[1]));
}
__device__ __forceinline__ void split1(float x, bf& h, bf& l) {
    h = __float2bfloat16(x);
    l = __float2bfloat16(x - __bfloat162float(h));
}
__device__ __forceinline__ uint32_t pack2(bf a, bf b) {
    __nv_bfloat162 t; t.x = a; t.y = b;
    return *(uint32_t*)&t;
}

// ---------------- HMMA split-bf16 GEMM (R9, batched) -------------------------
// EPI: 0 +bias->fp32 ; 1 +bias+resid->fp32 ; 3 raw->fp32 ;
//      4 +bias->split per-head bf16 ; 5 relu(+bias)->split flat
template<int BN, int EPI>
__global__ void __launch_bounds__(256) mma_gemm(
    const bf* __restrict__ Ahp, const bf* __restrict__ Alp,
    const bf* __restrict__ Bhp, const bf* __restrict__ Blp,
    const float* __restrict__ bias, const float* __restrict__ resid,
    float* __restrict__ C, int K, int ldc,
    long long sAz, long long sBz, long long sCzh, long long sCzl, int zshift,
    bf* __restrict__ Oh, bf* __restrict__ Ol)
{
    constexpr int BM = 128;
    constexpr int TN = BN / 16;
    constexpr int AE = BM * 32, BE = BN * 32, OFF_B = 4 * AE;
    extern __shared__ __align__(16) bf sm[];
    const int tid = threadIdx.x, lane = tid & 31, wid = tid >> 5;
    const int wm = wid & 3, wn = wid >> 2;
    const int z = blockIdx.z, bm = blockIdx.y * BM, bn = blockIdx.x * BN;
    const bf* gA[2] = { Ahp + (long long)z * sAz + (long long)bm * K,
                        Alp + (long long)z * sAz + (long long)bm * K };
    const bf* gB[2] = { Bhp + (long long)z * sBz + (long long)bn * K,
                        Blp + (long long)z * sBz + (long long)bn * K };
    const uint32_t smb = smem_u32(sm);

    float acc[2][TN][4];
#pragma unroll
    for (int i = 0; i < 2; i++)
#pragma unroll
        for (int j = 0; j < TN; j++)
#pragma unroll
            for (int q = 0; q < 4; q++) acc[i][j][q] = 0.f;

    auto prefetch = [&](int kt) {
        const int s = kt & 1;
        const long long kof = (long long)kt * 32;
#pragma unroll
        for (int h = 0; h < 2; h++) {
#pragma unroll
            for (int i = 0; i < 2; i++) {
                int u = tid + i * 256;
                int r = u >> 2, c = (u & 3) << 3;
                cpa16(smb + (uint32_t)(((s*2+h)*AE + swz(r, c)) * 2),
                      gA[h] + (long long)r * K + kof + c);
            }
#pragma unroll
            for (int i = 0; i < BN / 64; i++) {
                int u = tid + i * 256;
                int r = u >> 2, c = (u & 3) << 3;
                cpa16(smb + (uint32_t)((OFF_B + (s*2+h)*BE + swz(r, c)) * 2),
                      gB[h] + (long long)r * K + kof + c);
            }
        }
    };
    auto compute = [&](int s) {
        const uint32_t bA0 = smb + (uint32_t)((s*2    ) * AE * 2);
        const uint32_t bA1 = smb + (uint32_t)((s*2 + 1) * AE * 2);
        const uint32_t bB0 = smb + (uint32_t)((OFF_B + (s*2    ) * BE) * 2);
        const uint32_t bB1 = smb + (uint32_t)((OFF_B + (s*2 + 1) * BE) * 2);
#pragma unroll
        for (int ks = 0; ks < 2; ks++) {
            uint32_t aF[2][2][4], bF[2][TN/2][4];
            const int rA = wm * 32 + (lane & 15);
            const int cA = ks * 16 + (lane >> 4) * 8;
#pragma unroll
            for (int tm = 0; tm < 2; tm++) {
                int off = swz(rA + tm * 16, cA) * 2;
                ldsm4(aF[0][tm], bA0 + off);
                ldsm4(aF[1][tm], bA1 + off);
            }
            const int rB = wn * (BN/2) + ((lane >> 4) & 1) * 8 + (lane & 7);
            const int cB = ks * 16 + ((lane >> 3) & 1) * 8;
#pragma unroll
            for (int p = 0; p < TN/2; p++) {
                int off = swz(rB + p * 16, cB) * 2;
                ldsm4(bF[0][p], bB0 + off);
                ldsm4(bF[1][p], bB1 + off);
            }
#pragma unroll
            for (int tm = 0; tm < 2; tm++)
#pragma unroll
                for (int tn = 0; tn < TN; tn++) {
                    uint32_t* bh_ = &bF[0][tn >> 1][(tn & 1) * 2];
                    uint32_t* bl_ = &bF[1][tn >> 1][(tn & 1) * 2];
                    hmma(acc[tm][tn], aF[0][tm], bh_);
                    hmma(acc[tm][tn], aF[0][tm], bl_);
                    hmma(acc[tm][tn], aF[1][tm], bh_);
                }
        }
    };

    const int NT = K >> 5;
    prefetch(0);
    asm volatile("cp.async.commit_group;");
    for (int kt = 0; kt < NT; kt++) {
        if (kt + 1 < NT) {
            prefetch(kt + 1);
            asm volatile("cp.async.commit_group;");
            asm volatile("cp.async.wait_group 1;");
        } else {
            asm volatile("cp.async.wait_group 0;");
        }
        __syncthreads();
        compute(kt & 1);
        __syncthreads();
    }

    long long cbase = ((long long)(z >> zshift)) * sCzh
                    + ((long long)(z & ((1 << zshift) - 1))) * sCzl;
#pragma unroll
    for (int tm = 0; tm < 2; tm++)
#pragma unroll
        for (int tn = 0; tn < TN; tn++) {
            const int col = bn + wn * (BN/2) + tn * 8 + (lane & 3) * 2;
            const int row0 = bm + wm * 32 + tm * 16 + (lane >> 2);
            float2 bv = make_float2(0.f, 0.f);
            if (EPI != 3) bv = *(const float2*)(bias + col);
#pragma unroll
            for (int hf = 0; hf < 2; hf++) {
                const int row = row0 + hf * 8;
                float v0 = acc[tm][tn][hf*2]     + bv.x;
                float v1 = acc[tm][tn][hf*2 + 1] + bv.y;
                if (EPI == 5) { v0 = fmaxf(v0, 0.f); v1 = fmaxf(v1, 0.f); }
                if (EPI == 1) {
                    float2 rv = *(const float2*)(resid + (long long)row * ldc + col);
                    v0 += rv.x; v1 += rv.y;
                }
                if (EPI <= 3) {
                    float2 o; o.x = v0; o.y = v1;
                    *(float2*)(C + cbase + (long long)row * ldc + col) = o;
                } else {
                    bf h0,l0,h1,l1; split1(v0,h0,l0); split1(v1,h1,l1);
                    size_t dst;
                    if (EPI == 4) {
                        int hh = col >> 6, d = col & 63;
                        dst = ((((size_t)(row >> 10)) * 8 + hh) * 1024 + (row & 1023)) * 64 + d;
                    } else {
                        dst = (size_t)row * ldc + col;
                    }
                    *(uint32_t*)(Oh + dst) = pack2(h0, h1);
                    *(uint32_t*)(Ol + dst) = pack2(l0, l1);
                }
            }
        }
}

// ---------------- fused softmax + PV ----------------------------------------
// grid (8 mblocks, 64 bh), 256 thr, 2 CTA/SM.
// S fp32 [bh][1024][1024]; V split [bh][64][1024]; out split flat [B*S][512].
// smem: S bufs 2x(128x68 f32)=69632 @0 ; V bufs 2x16384 @69632 ; masks @102400
#define PV_SV 69632
#define PV_MK 102400
#define PVSM  102912

__global__ void __launch_bounds__(256, 2) pv_softmax(
    const float* __restrict__ S,
    const bf* __restrict__ Vth, const bf* __restrict__ Vtl,
    const int* __restrict__ mask, bf* __restrict__ Oh, bf* __restrict__ Ol)
{
    extern __shared__ __align__(16) char psm[];
    const int tid = threadIdx.x, lane = tid & 31, w = tid >> 5;
    const int mblk = blockIdx.x, bh = blockIdx.y, b = bh >> 3, h = bh & 7;
    const uint32_t smb = smem_u32(psm);
    const float* Sg = S + (size_t)bh * 1048576 + (size_t)mblk * 131072;  // 128*1024

    auto pf = [&](int kc) {
        int buf = kc & 1;
#pragma unroll
        for (int i = 0; i < 8; i++) {                 // S chunk 128x64 fp32
            int u = i * 256 + tid;
            int r = u >> 4, c4 = u & 15;
            cpa16(smb + (uint32_t)(buf * 34816 + r * 272 + c4 * 16),
                  Sg + (size_t)r * 1024 + kc * 64 + c4 * 4);
        }
#pragma unroll
        for (int i = 0; i < 4; i++) {                 // V chunk [64 dims][64 keys] hi/lo
            int u = i * 256 + tid;
            int hl = u >> 9, u2 = u & 511, r = u2 >> 3, c = (u2 & 7) << 3;
            cpa16(smb + (uint32_t)(PV_SV + buf * 16384 + hl * 8192 + swzK(r, c) * 2),
                  (hl ? Vtl : Vth) + ((size_t)bh * 64 + r) * 1024 + kc * 64 + c);
        }
        if (tid < 64)
            cpa4(smb + (uint32_t)(PV_MK + buf * 256 + tid * 4),
                 mask + b * 1024 + kc * 64 + tid);
    };
    pf(0);
    asm volatile("cp.async.commit_group;");

    float acc_o[8][4];
#pragma unroll
    for (int i = 0; i < 8; i++)
#pragma unroll
        for (int q = 0; q < 4; q++) acc_o[i][q] = 0.f;
    float mA = -INFINITY, mB = -INFINITY, lA = 0.f, lB = 0.f;
    const int r0 = w * 16 + (lane >> 2);
    const int ccol = (lane & 3) * 2;

    for (int kc = 0; kc < 16; kc++) {
        if (kc < 15) {
            pf(kc + 1);
            asm volatile("cp.async.commit_group;");
            asm volatile("cp.async.wait_group 1;");
        } else {
            asm volatile("cp.async.wait_group 0;");
        }
        __syncthreads();
        const int buf = kc & 1;
        const int* mrow = (const int*)(psm + PV_MK + buf * 256);
        const char* sbuf = psm + buf * 34816;
        // ---- load S fragments + mask + scale ----
        float s[8][4];
#pragma unroll
        for (int tn = 0; tn < 8; tn++) {
            int col = tn * 8 + ccol;
            float2 v0 = *(const float2*)(sbuf + ((size_t)r0 * 68 + col) * 4);
            float2 v1 = *(const float2*)(sbuf + ((size_t)(r0 + 8) * 68 + col) * 4);
            bool k0 = mrow[col] != 0, k1 = mrow[col + 1] != 0;
            s[tn][0] = k0 ? v0.x * 0.125f : -1e10f;
            s[tn][1] = k1 ? v0.y * 0.125f : -1e10f;
            s[tn][2] = k0 ? v1.x * 0.125f : -1e10f;
            s[tn][3] = k1 ? v1.y * 0.125f : -1e10f;
        }
        // ---- online softmax (verified flash-v2 code) ----
        float cmA = -INFINITY, cmB = -INFINITY;
#pragma unroll
        for (int tn = 0; tn < 8; tn++) {
            cmA = fmaxf(cmA, fmaxf(s[tn][0], s[tn][1]));
            cmB = fmaxf(cmB, fmaxf(s[tn][2], s[tn][3]));
        }
        cmA = fmaxf(cmA, __shfl_xor_sync(~0u, cmA, 1));
        cmA = fmaxf(cmA, __shfl_xor_sync(~0u, cmA, 2));
        cmB = fmaxf(cmB, __shfl_xor_sync(~0u, cmB, 1));
        cmB = fmaxf(cmB, __shfl_xor_sync(~0u, cmB, 2));
        float mAn = fmaxf(mA, cmA), mBn = fmaxf(mB, cmB);
        float corA = __expf(mA - mAn), corB = __expf(mB - mBn);
        float sumA = 0.f, sumB = 0.f;
#pragma unroll
        for (int tn = 0; tn < 8; tn++) {
            s[tn][0] = __expf(s[tn][0] - mAn); s[tn][1] = __expf(s[tn][1] - mAn);
            s[tn][2] = __expf(s[tn][2] - mBn); s[tn][3] = __expf(s[tn][3] - mBn);
            sumA += s[tn][0] + s[tn][1];
            sumB += s[tn][2] + s[tn][3];
        }
        sumA += __shfl_xor_sync(~0u, sumA, 1); sumA += __shfl_xor_sync(~0u, sumA, 2);
        sumB += __shfl_xor_sync(~0u, sumB, 1); sumB += __shfl_xor_sync(~0u, sumB, 2);
        lA = lA * corA + sumA; lB = lB * corB + sumB;
        mA = mAn; mB = mBn;
#pragma unroll
        for (int tn = 0; tn < 8; tn++) {
            acc_o[tn][0] *= corA; acc_o[tn][1] *= corA;
            acc_o[tn][2] *= corB; acc_o[tn][3] *= corB;
        }
        // ---- O += P V ----
        const uint32_t vb0 = smb + (uint32_t)(PV_SV + buf * 16384);
        const uint32_t vb1 = vb0 + 8192;
#pragma unroll
        for (int ks2 = 0; ks2 < 4; ks2++) {
            float* t0 = s[2 * ks2];
            float* t1 = s[2 * ks2 + 1];
            uint32_t aH[4], aL[4];
#pragma unroll
            for (int j = 0; j < 2; j++) {
                bf ha0,la0,ha1,la1,hb0,lb0,hb1,lb1;
                split1(t0[j*2],   ha0, la0); split1(t0[j*2+1], ha1, la1);
                split1(t1[j*2],   hb0, lb0); split1(t1[j*2+1], hb1, lb1);
                aH[j]   = pack2(ha0, ha1); aL[j]   = pack2(la0, la1);
                aH[j+2] = pack2(hb0, hb1); aL[j+2] = pack2(lb0, lb1);
            }
            const int cB = ks2 * 16 + ((lane >> 3) & 1) * 8;
#pragma unroll
            for (int pn = 0; pn < 4; pn++) {
                uint32_t vh_[4], vl_[4];
                int rB = pn * 16 + ((lane >> 4) & 1) * 8 + (lane & 7);
                int off = swzK(rB, cB) * 2;
                ldsm4(vh_, vb0 + off);
                ldsm4(vl_, vb1 + off);
#pragma unroll
                for (int hf = 0; hf < 2; hf++) {
                    int tn = pn * 2 + hf;
                    hmma(acc_o[tn], aH, vh_ + hf * 2);
                    hmma(acc_o[tn], aH, vl_ + hf * 2);
                    hmma(acc_o[tn], aL, vh_ + hf * 2);
                }
            }
        }
        __syncthreads();
    }
    // ---- write O (split bf16, flat [B*S][512]) ----
    float invA = 1.f / lA, invB = 1.f / lB;
    const int row0 = mblk * 128 + w * 16 + (lane >> 2);
#pragma unroll
    for (int tn = 0; tn < 8; tn++) {
        int col = tn * 8 + (lane & 3) * 2;
        size_t f0 = ((size_t)b * 1024 + row0) * 512 + h * 64 + col;
        size_t f1 = f0 + 8 * 512;
        float o0 = acc_o[tn][0] * invA, o1 = acc_o[tn][1] * invA;
        float o2 = acc_o[tn][2] * invB, o3 = acc_o[tn][3] * invB;
        bf h0,l0,h1,l1,h2,l2,h3,l3;
        split1(o0,h0,l0); split1(o1,h1,l1); split1(o2,h2,l2); split1(o3,h3,l3);
        *(uint32_t*)(Oh + f0) = pack2(h0, h1);
        *(uint32_t*)(Ol + f0) = pack2(l0, l1);
        *(uint32_t*)(Oh + f1) = pack2(h2, h3);
        *(uint32_t*)(Ol + f1) = pack2(l2, l3);
    }
}

// ---------------- conversions -----------------------------------------------
__device__ __forceinline__ void st4(bf* oh, bf* ol, size_t o, float a, float b, float c, float d) {
    bf h0,h1,h2,h3,l0,l1,l2,l3;
    split1(a,h0,l0); split1(b,h1,l1); split1(c,h2,l2); split1(d,h3,l3);
    *(uint32_t*)(oh + o)     = pack2(h0, h1);
    *(uint32_t*)(oh + o + 2) = pack2(h2, h3);
    *(uint32_t*)(ol + o)     = pack2(l0, l1);
    *(uint32_t*)(ol + o + 2) = pack2(l2, l3);
}
__global__ void __launch_bounds__(256) split_flat(const float* __restrict__ in, bf* oh, bf* ol) {
    size_t i4 = ((size_t)blockIdx.x * 256 + threadIdx.x) * 4;
    float4 v = *(const float4*)(in + i4);
    st4(oh, ol, i4, v.x, v.y, v.z, v.w);
}
__global__ void __launch_bounds__(256) split_vt(const float* __restrict__ in, bf* oh, bf* ol) {
    __shared__ float t[32][33];
    int s0 = blockIdx.x * 32, d0 = blockIdx.y * 32, bh = blockIdx.z;
    int b = bh >> 3, h = bh & 7;
    int tx = threadIdx.x, ty = threadIdx.y;
#pragma unroll
    for (int j = 0; j < 4; j++)
        t[ty + j*8][tx] = in[((size_t)(b * SS + s0 + ty + j*8)) * 512 + h * 64 + d0 + tx];
    __syncthreads();
#pragma unroll
    for (int j = 0; j < 4; j++) {
        int d = d0 + ty + j*8;
        bf hh, ll; split1(t[tx][ty + j*8], hh, ll);
        size_t o = ((size_t)bh * 64 + d) * SS + s0 + tx;
        oh[o] = hh; ol[o] = ll;
    }
}
__global__ void __launch_bounds__(256) split_whead(const float* __restrict__ in, bf* oh, bf* ol) {
    __shared__ float t[32][33];
    int k0 = blockIdx.x * 32, d0 = blockIdx.y * 32, h = blockIdx.z;
    int tx = threadIdx.x, ty = threadIdx.y;
#pragma unroll
    for (int j = 0; j < 4; j++)
        t[ty + j*8][tx] = in[(size_t)h * 32768 + (size_t)(k0 + ty + j*8) * 64 + d0 + tx];
    __syncthreads();
#pragma unroll
    for (int j = 0; j < 4; j++) {
        int d = d0 + ty + j*8;
        bf hh, ll; split1(t[tx][ty + j*8], hh, ll);
        size_t o = ((size_t)(h * 64 + d)) * 512 + k0 + tx;
        oh[o] = hh; ol[o] = ll;
    }
}

// ---------------- LayerNorm --------------------------------------------------
__global__ void __launch_bounds__(256) ln_partial_kernel(const float* __restrict__ X) {
    int b = blockIdx.x >> 8, c = blockIdx.x & 255, tid = threadIdx.x;
    const float* p = X + (size_t)b * SD + (size_t)c * 2048;
    float s = 0.f, s2 = 0.f;
#pragma unroll
    for (int i = 0; i < 8; i++) { float v = p[tid + i*256]; s += v; s2 += v*v; }
    __shared__ float sh[256], sh2[256];
    sh[tid] = s; sh2[tid] = s2; __syncthreads();
    for (int o = 128; o; o >>= 1) {
        if (tid < o) { sh[tid] += sh[tid+o]; sh2[tid] += sh2[tid+o]; }
        __syncthreads();
    }
    if (tid == 0) { g_psum[blockIdx.x] = sh[0]; g_psumsq[blockIdx.x] = sh2[0]; }
}
__global__ void __launch_bounds__(256) ln_final_kernel() {
    int b = blockIdx.x, tid = threadIdx.x;
    __shared__ float sh[256], sh2[256];
    sh[tid] = g_psum[b*256 + tid]; sh2[tid] = g_psumsq[b*256 + tid];
    __syncthreads();
    for (int o = 128; o; o >>= 1) {
        if (tid < o) { sh[tid] += sh[tid+o]; sh2[tid] += sh2[tid+o]; }
        __syncthreads();
    }
    if (tid == 0) {
        float mean = sh[0] / (float)SD;
        float var = sh2[0] / (float)SD - mean * mean;
        g_mr[2*b] = mean; g_mr[2*b+1] = rsqrtf(var + 1e-6f);
    }
}
__global__ void __launch_bounds__(256) ln_apply_split(
    const float* __restrict__ X, const float* __restrict__ w,
    const float* __restrict__ bb, float* __restrict__ Y, bf* oh, bf* ol)
{
    size_t base = ((size_t)blockIdx.x * 256 + threadIdx.x) * 4;
    int b = (int)(base / SD); size_t sd = base % SD;
    float mean = g_mr[2*b], rstd = g_mr[2*b+1];
    float4 xv = *(const float4*)(X + base);
    float4 wv = *(const float4*)(w + sd);
    float4 bv = *(const float4*)(bb + sd);
    float4 yv;
    yv.x = (xv.x-mean)*rstd*wv.x + bv.x; yv.y = (xv.y-mean)*rstd*wv.y + bv.y;
    yv.z = (xv.z-mean)*rstd*wv.z + bv.z; yv.w = (xv.w-mean)*rstd*wv.w + bv.w;
    *(float4*)(Y + base) = yv;
    st4(oh, ol, base, yv.x, yv.y, yv.z, yv.w);
}

// ---------------- host driver ------------------------------------------------
#define SM128 65536

struct P {
    float *v, *res, *x1, *x2, *S;
    bf *ah,*al,*bh,*bl,*qh,*ql,*kh,*kl,*vth,*vtl,*ffh,*ffl;
};

static void run_ln(const float* X, const float* w, const float* b, float* Y, bf* oh, bf* ol) {
    ln_partial_kernel<<<BB*256, 256>>>(X);
    ln_final_kernel<<<BB, 256>>>();
    ln_apply_split<<<4096, 256>>>(X, w, b, Y, oh, ol);
}

// q input split already in p.ah/p.al on entry
static void mha_stage(P& p, bool kv_from_y, const float* y,
    const float* wq, const float* bq, const float* wk, const float* bk,
    const float* wv, const float* bv, const float* wo, const float* bo,
    const int* mask, const float* resid, float* outres)
{
    dim3 gP(4, 64), gW(16, 2, 8), bW(32, 8), gVT(32, 2, 64);
    split_whead<<<gW, bW>>>(wq, p.bh, p.bl);
    mma_gemm<128,4><<<gP, 256, SM128>>>(p.ah, p.al, p.bh, p.bl, bq, nullptr, nullptr,
        512, 512, 0,0,0,0,0, p.qh, p.ql);
    if (kv_from_y) split_flat<<<4096, 256>>>(y, p.ah, p.al);
    split_whead<<<gW, bW>>>(wk, p.bh, p.bl);
    mma_gemm<128,4><<<gP, 256, SM128>>>(p.ah, p.al, p.bh, p.bl, bk, nullptr, nullptr,
        512, 512, 0,0,0,0,0, p.kh, p.kl);
    split_whead<<<gW, bW>>>(wv, p.bh, p.bl);
    mma_gemm<128,0><<<gP, 256, SM128>>>(p.ah, p.al, p.bh, p.bl, bv, nullptr, p.v,
        512, 512, 0,0,0,0,0, nullptr, nullptr);
    split_vt<<<gVT, bW>>>(p.v, p.vth, p.vtl);

    // S = Q K^T (batched over bh)
    mma_gemm<128,3><<<dim3(8,8,64), 256, SM128>>>(p.qh, p.ql, p.kh, p.kl, nullptr, nullptr,
        p.S, 64, 1024, 65536, 65536, 1048576, 0, 0, nullptr, nullptr);
    // fused mask+softmax+PV -> split att output in ah/al
    pv_softmax<<<dim3(8, 64), 256, PVSM>>>(p.S, p.vth, p.vtl, mask, p.ah, p.al);

    split_flat<<<256, 256>>>(wo, p.bh, p.bl);
    mma_gemm<128,1><<<gP, 256, SM128>>>(p.ah, p.al, p.bh, p.bl, bo, resid, outres,
        512, 512, 0,0,0,0,0, nullptr, nullptr);
}

extern "C" void kernel_launch(void* const* d_in, const int* in_sizes, int n_in,
                              void* d_out, int out_size)
{
#define FP(i) ((const float*)d_in[i])
    const int* src_mask = (const int*)d_in[2];
    const int* trg_mask = (const int*)d_in[3];
    float* out = (float*)d_out;

    cudaFuncSetAttribute(mma_gemm<128,0>, cudaFuncAttributeMaxDynamicSharedMemorySize, SM128);
    cudaFuncSetAttribute(mma_gemm<128,1>, cudaFuncAttributeMaxDynamicSharedMemorySize, SM128);
    cudaFuncSetAttribute(mma_gemm<128,3>, cudaFuncAttributeMaxDynamicSharedMemorySize, SM128);
    cudaFuncSetAttribute(mma_gemm<128,4>, cudaFuncAttributeMaxDynamicSharedMemorySize, SM128);
    cudaFuncSetAttribute(mma_gemm<128,5>, cudaFuncAttributeMaxDynamicSharedMemorySize, SM128);
    cudaFuncSetAttribute(pv_softmax,      cudaFuncAttributeMaxDynamicSharedMemorySize, PVSM);

    P p;
    cudaGetSymbolAddress((void**)&p.v,   g_v);   cudaGetSymbolAddress((void**)&p.res, g_res);
    cudaGetSymbolAddress((void**)&p.x1,  g_x1);  cudaGetSymbolAddress((void**)&p.x2,  g_x2);
    cudaGetSymbolAddress((void**)&p.S,   g_S);
    cudaGetSymbolAddress((void**)&p.ah,  g_ah);  cudaGetSymbolAddress((void**)&p.al,  g_al);
    cudaGetSymbolAddress((void**)&p.bh,  g_bh);  cudaGetSymbolAddress((void**)&p.bl,  g_bl);
    cudaGetSymbolAddress((void**)&p.qh,  g_qh);  cudaGetSymbolAddress((void**)&p.ql,  g_ql);
    cudaGetSymbolAddress((void**)&p.kh,  g_kh);  cudaGetSymbolAddress((void**)&p.kl,  g_kl);
    cudaGetSymbolAddress((void**)&p.vth, g_vth); cudaGetSymbolAddress((void**)&p.vtl, g_vtl);
    cudaGetSymbolAddress((void**)&p.ffh, g_ffh); cudaGetSymbolAddress((void**)&p.ffl, g_ffl);

    // ---- stage 1: self-attention ----
    split_flat<<<4096, 256>>>(FP(0), p.ah, p.al);
    mha_stage(p, false, nullptr, FP(4), FP(5), FP(6), FP(7), FP(8), FP(9), FP(10), FP(11),
              trg_mask, FP(0), p.res);
    run_ln(p.res, FP(24), FP(25), p.x1, p.ah, p.al);

    // ---- stage 2: cross-attention ----
    mha_stage(p, true, FP(1), FP(12), FP(13), FP(14), FP(15), FP(16), FP(17), FP(18), FP(19),
              src_mask, p.x1, p.res);
    run_ln(p.res, FP(26), FP(27), p.x2, p.ah, p.al);

    // ---- stage 3: FFN ----
    split_flat<<<1024, 256>>>(FP(20), p.bh, p.bl);
    mma_gemm<128,5><<<dim3(16, 64), 256, SM128>>>(p.ah, p.al, p.bh, p.bl, FP(21), nullptr,
        nullptr, 512, 2048, 0,0,0,0,0, p.ffh, p.ffl);
    split_flat<<<1024, 256>>>(FP(22), p.bh, p.bl);
    mma_gemm<128,1><<<dim3(4, 64), 256, SM128>>>(p.ffh, p.ffl, p.bh, p.bl, FP(23), p.x2,
        p.res, 2048, 512, 0,0,0,0,0, nullptr, nullptr);
    run_ln(p.res, FP(28), FP(29), out, p.ah, p.al);
}

// round 16
// speedup vs baseline: 2.3771x; 1.7927x over previous
#include <cuda_runtime.h>
#include <cuda_fp16.h>
#include <math.h>
#include <stdint.h>

#define BB 8
#define SS 1024
#define DD 512
#define HH 8
#define DFFN 2048
#define MROWS (BB*SS)
#define SD (SS*DD)
#define NBH (BB*HH)
typedef __half hf;

// ---------------- scratch ---------------------------------------------------
__device__ __align__(128) float g_v  [MROWS*DD];
__device__ __align__(128) float g_res[MROWS*DD];
__device__ __align__(128) float g_x1 [MROWS*DD];
__device__ __align__(128) float g_x2 [MROWS*DD];
__device__ __align__(128) float g_S  [(size_t)NBH*SS*SS];
__device__ __align__(128) hf g_a [MROWS*DFFN];
__device__ __align__(128) hf g_b [DFFN*DD];
__device__ __align__(128) hf g_q [NBH*SS*64];
__device__ __align__(128) hf g_k [NBH*SS*64];
__device__ __align__(128) hf g_vt[NBH*64*SS];
__device__ __align__(128) hf g_ff[MROWS*DFFN];
__device__ float g_psum[BB*256], g_psumsq[BB*256], g_mr[2*BB];

// ---------------- helpers ---------------------------------------------------
__device__ __forceinline__ uint32_t smem_u32(const void* p) {
    uint32_t a;
    asm("{ .reg .u64 t; cvta.to.shared.u64 t, %1; cvt.u32.u64 %0, t; }" : "=r"(a) : "l"(p));
    return a;
}
__device__ __forceinline__ int swz(int r, int c) {        // 32-elem rows (GEMM)
    return r * 32 + ((((c >> 3) ^ ((r ^ (r >> 1)) & 3)) << 3) | (c & 7));
}
__device__ __forceinline__ int swzK(int r, int c) {       // 64-elem rows
    return r * 64 + ((((c >> 3) ^ (r & 7)) << 3) | (c & 7));
}
__device__ __forceinline__ void cpa16(uint32_t d, const void* s) {
    asm volatile("cp.async.cg.shared.global [%0], [%1], 16;" :: "r"(d), "l"(s));
}
__device__ __forceinline__ void cpa4(uint32_t d, const void* s) {
    asm volatile("cp.async.ca.shared.global [%0], [%1], 4;" :: "r"(d), "l"(s));
}
__device__ __forceinline__ void ldsm4(uint32_t* r, uint32_t a) {
    asm volatile("ldmatrix.sync.aligned.m8n8.x4.shared.b16 {%0,%1,%2,%3}, [%4];"
        : "=r"(r[0]), "=r"(r[1]), "=r"(r[2]), "=r"(r[3]) : "r"(a));
}
__device__ __forceinline__ void hmma(float* d, const uint32_t* a, const uint32_t* b) {
    asm volatile("mma.sync.aligned.m16n8k16.row.col.f32.f16.f16.f32 "
        "{%0,%1,%2,%3}, {%4,%5,%6,%7}, {%8,%9}, {%0,%1,%2,%3};"
        : "+f"(d[0]), "+f"(d[1]), "+f"(d[2]), "+f"(d[3])
        : "r"(a[0]), "r"(a[1]), "r"(a[2]), "r"(a[3]), "r"(b[0]), "r"(b[1]));
}
__device__ __forceinline__ uint32_t pack2h(hf a, hf b) {
    __half2 t; t.x = a; t.y = b;
    return *(uint32_t*)&t;
}
__device__ __forceinline__ void st4h(hf* o, size_t off, float a, float b, float c, float d) {
    *(uint32_t*)(o + off)     = pack2h(__float2half_rn(a), __float2half_rn(b));
    *(uint32_t*)(o + off + 2) = pack2h(__float2half_rn(c), __float2half_rn(d));
}

// ---------------- fp16 HMMA GEMM (BM=128, BK=32, 2-stage) --------------------
// C = A[.,K] @ B[N,K]^T ; batched over blockIdx.z
// EPI: 0 +bias->fp32 ; 1 +bias+resid->fp32 ; 3 raw->fp32 ;
//      4 +bias->per-head fp16 ; 5 relu(+bias)->fp16 flat
template<int BN, int EPI>
__global__ void __launch_bounds__(256) mma_gemm(
    const hf* __restrict__ Ap, const hf* __restrict__ Bp,
    const float* __restrict__ bias, const float* __restrict__ resid,
    float* __restrict__ C, int K, int ldc,
    long long sAz, long long sBz, long long sCzh, long long sCzl, int zshift,
    hf* __restrict__ Oh)
{
    constexpr int BM = 128;
    constexpr int TN = BN / 16;
    constexpr int AE = BM * 32, BE = BN * 32, OFF_B = 2 * AE;
    extern __shared__ __align__(16) hf sm[];
    const int tid = threadIdx.x, lane = tid & 31, wid = tid >> 5;
    const int wm = wid & 3, wn = wid >> 2;
    const int z = blockIdx.z, bm = blockIdx.y * BM, bn = blockIdx.x * BN;
    const hf* gA = Ap + (long long)z * sAz + (long long)bm * K;
    const hf* gB = Bp + (long long)z * sBz + (long long)bn * K;
    const uint32_t smb = smem_u32(sm);

    float acc[2][TN][4];
#pragma unroll
    for (int i = 0; i < 2; i++)
#pragma unroll
        for (int j = 0; j < TN; j++)
#pragma unroll
            for (int q = 0; q < 4; q++) acc[i][j][q] = 0.f;

    auto prefetch = [&](int kt) {
        const int s = kt & 1;
        const long long kof = (long long)kt * 32;
#pragma unroll
        for (int i = 0; i < 2; i++) {
            int u = tid + i * 256;
            int r = u >> 2, c = (u & 3) << 3;
            cpa16(smb + (uint32_t)((s * AE + swz(r, c)) * 2),
                  gA + (long long)r * K + kof + c);
        }
#pragma unroll
        for (int i = 0; i < BN / 64; i++) {
            int u = tid + i * 256;
            int r = u >> 2, c = (u & 3) << 3;
            cpa16(smb + (uint32_t)((OFF_B + s * BE + swz(r, c)) * 2),
                  gB + (long long)r * K + kof + c);
        }
    };
    auto compute = [&](int s) {
        const uint32_t bA = smb + (uint32_t)(s * AE * 2);
        const uint32_t bB = smb + (uint32_t)((OFF_B + s * BE) * 2);
#pragma unroll
        for (int ks = 0; ks < 2; ks++) {
            uint32_t aF[2][4], bF[TN/2][4];
            const int rA = wm * 32 + (lane & 15);
            const int cA = ks * 16 + (lane >> 4) * 8;
#pragma unroll
            for (int tm = 0; tm < 2; tm++)
                ldsm4(aF[tm], bA + swz(rA + tm * 16, cA) * 2);
            const int rB = wn * (BN/2) + ((lane >> 4) & 1) * 8 + (lane & 7);
            const int cB = ks * 16 + ((lane >> 3) & 1) * 8;
#pragma unroll
            for (int p = 0; p < TN/2; p++)
                ldsm4(bF[p], bB + swz(rB + p * 16, cB) * 2);
#pragma unroll
            for (int tm = 0; tm < 2; tm++)
#pragma unroll
                for (int tn = 0; tn < TN; tn++)
                    hmma(acc[tm][tn], aF[tm], &bF[tn >> 1][(tn & 1) * 2]);
        }
    };

    const int NT = K >> 5;
    prefetch(0);
    asm volatile("cp.async.commit_group;");
    for (int kt = 0; kt < NT; kt++) {
        if (kt + 1 < NT) {
            prefetch(kt + 1);
            asm volatile("cp.async.commit_group;");
            asm volatile("cp.async.wait_group 1;");
        } else {
            asm volatile("cp.async.wait_group 0;");
        }
        __syncthreads();
        compute(kt & 1);
        __syncthreads();
    }

    long long cbase = ((long long)(z >> zshift)) * sCzh
                    + ((long long)(z & ((1 << zshift) - 1))) * sCzl;
#pragma unroll
    for (int tm = 0; tm < 2; tm++)
#pragma unroll
        for (int tn = 0; tn < TN; tn++) {
            const int col = bn + wn * (BN/2) + tn * 8 + (lane & 3) * 2;
            const int row0 = bm + wm * 32 + tm * 16 + (lane >> 2);
            float2 bv = make_float2(0.f, 0.f);
            if (EPI != 3) bv = *(const float2*)(bias + col);
#pragma unroll
            for (int hfi = 0; hfi < 2; hfi++) {
                const int row = row0 + hfi * 8;
                float v0 = acc[tm][tn][hfi*2]     + bv.x;
                float v1 = acc[tm][tn][hfi*2 + 1] + bv.y;
                if (EPI == 5) { v0 = fmaxf(v0, 0.f); v1 = fmaxf(v1, 0.f); }
                if (EPI == 1) {
                    float2 rv = *(const float2*)(resid + (long long)row * ldc + col);
                    v0 += rv.x; v1 += rv.y;
                }
                if (EPI <= 3) {
                    float2 o; o.x = v0; o.y = v1;
                    *(float2*)(C + cbase + (long long)row * ldc + col) = o;
                } else {
                    size_t dst;
                    if (EPI == 4) {
                        int hh = col >> 6, d = col & 63;
                        dst = ((((size_t)(row >> 10)) * 8 + hh) * 1024 + (row & 1023)) * 64 + d;
                    } else {
                        dst = (size_t)row * ldc + col;
                    }
                    *(uint32_t*)(Oh + dst) =
                        pack2h(__float2half_rn(v0), __float2half_rn(v1));
                }
            }
        }
}

// ---------------- fused softmax + PV (fp16 V / fp16 out) ---------------------
// grid (8 mblocks, 64 bh), 256 thr, 2 CTA/SM.
// smem: S bufs 2x(128x68 f32)=69632 @0 ; V bufs 2x8192 @69632 ; masks @86016
#define PV_SV 69632
#define PV_MK 86016
#define PVSM  86528

__global__ void __launch_bounds__(256, 2) pv_softmax(
    const float* __restrict__ S, const hf* __restrict__ Vt,
    const int* __restrict__ mask, hf* __restrict__ Oh)
{
    extern __shared__ __align__(16) char psm[];
    const int tid = threadIdx.x, lane = tid & 31, w = tid >> 5;
    const int mblk = blockIdx.x, bh = blockIdx.y, b = bh >> 3, h = bh & 7;
    const uint32_t smb = smem_u32(psm);
    const float* Sg = S + (size_t)bh * 1048576 + (size_t)mblk * 131072;

    auto pf = [&](int kc) {
        int buf = kc & 1;
#pragma unroll
        for (int i = 0; i < 8; i++) {                 // S chunk 128x64 fp32
            int u = i * 256 + tid;
            int r = u >> 4, c4 = u & 15;
            cpa16(smb + (uint32_t)(buf * 34816 + r * 272 + c4 * 16),
                  Sg + (size_t)r * 1024 + kc * 64 + c4 * 4);
        }
#pragma unroll
        for (int i = 0; i < 2; i++) {                 // V chunk [64 d][64 keys] fp16
            int u = i * 256 + tid;
            int r = u >> 3, c = (u & 7) << 3;
            cpa16(smb + (uint32_t)(PV_SV + buf * 8192 + swzK(r, c) * 2),
                  Vt + ((size_t)bh * 64 + r) * 1024 + kc * 64 + c);
        }
        if (tid < 64)
            cpa4(smb + (uint32_t)(PV_MK + buf * 256 + tid * 4),
                 mask + b * 1024 + kc * 64 + tid);
    };
    pf(0);
    asm volatile("cp.async.commit_group;");

    float acc_o[8][4];
#pragma unroll
    for (int i = 0; i < 8; i++)
#pragma unroll
        for (int q = 0; q < 4; q++) acc_o[i][q] = 0.f;
    float mA = -INFINITY, mB = -INFINITY, lA = 0.f, lB = 0.f;
    const int r0 = w * 16 + (lane >> 2);
    const int ccol = (lane & 3) * 2;

    for (int kc = 0; kc < 16; kc++) {
        if (kc < 15) {
            pf(kc + 1);
            asm volatile("cp.async.commit_group;");
            asm volatile("cp.async.wait_group 1;");
        } else {
            asm volatile("cp.async.wait_group 0;");
        }
        __syncthreads();
        const int buf = kc & 1;
        const int* mrow = (const int*)(psm + PV_MK + buf * 256);
        const char* sbuf = psm + buf * 34816;
        float s[8][4];
#pragma unroll
        for (int tn = 0; tn < 8; tn++) {
            int col = tn * 8 + ccol;
            float2 v0 = *(const float2*)(sbuf + ((size_t)r0 * 68 + col) * 4);
            float2 v1 = *(const float2*)(sbuf + ((size_t)(r0 + 8) * 68 + col) * 4);
            bool k0 = mrow[col] != 0, k1 = mrow[col + 1] != 0;
            s[tn][0] = k0 ? v0.x * 0.125f : -1e10f;
            s[tn][1] = k1 ? v0.y * 0.125f : -1e10f;
            s[tn][2] = k0 ? v1.x * 0.125f : -1e10f;
            s[tn][3] = k1 ? v1.y * 0.125f : -1e10f;
        }
        float cmA = -INFINITY, cmB = -INFINITY;
#pragma unroll
        for (int tn = 0; tn < 8; tn++) {
            cmA = fmaxf(cmA, fmaxf(s[tn][0], s[tn][1]));
            cmB = fmaxf(cmB, fmaxf(s[tn][2], s[tn][3]));
        }
        cmA = fmaxf(cmA, __shfl_xor_sync(~0u, cmA, 1));
        cmA = fmaxf(cmA, __shfl_xor_sync(~0u, cmA, 2));
        cmB = fmaxf(cmB, __shfl_xor_sync(~0u, cmB, 1));
        cmB = fmaxf(cmB, __shfl_xor_sync(~0u, cmB, 2));
        float mAn = fmaxf(mA, cmA), mBn = fmaxf(mB, cmB);
        float corA = __expf(mA - mAn), corB = __expf(mB - mBn);
        float sumA = 0.f, sumB = 0.f;
#pragma unroll
        for (int tn = 0; tn < 8; tn++) {
            s[tn][0] = __expf(s[tn][0] - mAn); s[tn][1] = __expf(s[tn][1] - mAn);
            s[tn][2] = __expf(s[tn][2] - mBn); s[tn][3] = __expf(s[tn][3] - mBn);
            sumA += s[tn][0] + s[tn][1];
            sumB += s[tn][2] + s[tn][3];
        }
        sumA += __shfl_xor_sync(~0u, sumA, 1); sumA += __shfl_xor_sync(~0u, sumA, 2);
        sumB += __shfl_xor_sync(~0u, sumB, 1); sumB += __shfl_xor_sync(~0u, sumB, 2);
        lA = lA * corA + sumA; lB = lB * corB + sumB;
        mA = mAn; mB = mBn;
#pragma unroll
        for (int tn = 0; tn < 8; tn++) {
            acc_o[tn][0] *= corA; acc_o[tn][1] *= corA;
            acc_o[tn][2] *= corB; acc_o[tn][3] *= corB;
        }
        const uint32_t vb = smb + (uint32_t)(PV_SV + buf * 8192);
#pragma unroll
        for (int ks2 = 0; ks2 < 4; ks2++) {
            float* t0 = s[2 * ks2];
            float* t1 = s[2 * ks2 + 1];
            uint32_t aP[4];
            aP[0] = pack2h(__float2half_rn(t0[0]), __float2half_rn(t0[1]));
            aP[1] = pack2h(__float2half_rn(t0[2]), __float2half_rn(t0[3]));
            aP[2] = pack2h(__float2half_rn(t1[0]), __float2half_rn(t1[1]));
            aP[3] = pack2h(__float2half_rn(t1[2]), __float2half_rn(t1[3]));
            const int cB = ks2 * 16 + ((lane >> 3) & 1) * 8;
#pragma unroll
            for (int pn = 0; pn < 4; pn++) {
                uint32_t vF[4];
                int rB = pn * 16 + ((lane >> 4) & 1) * 8 + (lane & 7);
                ldsm4(vF, vb + swzK(rB, cB) * 2);
#pragma unroll
                for (int hfi = 0; hfi < 2; hfi++)
                    hmma(acc_o[pn * 2 + hfi], aP, vF + hfi * 2);
            }
        }
        __syncthreads();
    }
    float invA = 1.f / lA, invB = 1.f / lB;
    const int row0 = mblk * 128 + w * 16 + (lane >> 2);
#pragma unroll
    for (int tn = 0; tn < 8; tn++) {
        int col = tn * 8 + (lane & 3) * 2;
        size_t f0 = ((size_t)b * 1024 + row0) * 512 + h * 64 + col;
        size_t f1 = f0 + 8 * 512;
        *(uint32_t*)(Oh + f0) = pack2h(__float2half_rn(acc_o[tn][0] * invA),
                                       __float2half_rn(acc_o[tn][1] * invA));
        *(uint32_t*)(Oh + f1) = pack2h(__float2half_rn(acc_o[tn][2] * invB),
                                       __float2half_rn(acc_o[tn][3] * invB));
    }
}

// ---------------- conversions -----------------------------------------------
__global__ void __launch_bounds__(256) cvt_flat(const float* __restrict__ in, hf* o) {
    size_t i4 = ((size_t)blockIdx.x * 256 + threadIdx.x) * 4;
    float4 v = *(const float4*)(in + i4);
    st4h(o, i4, v.x, v.y, v.z, v.w);
}
__global__ void __launch_bounds__(256) cvt_vt(const float* __restrict__ in, hf* o) {
    __shared__ float t[32][33];
    int s0 = blockIdx.x * 32, d0 = blockIdx.y * 32, bh = blockIdx.z;
    int b = bh >> 3, h = bh & 7;
    int tx = threadIdx.x, ty = threadIdx.y;
#pragma unroll
    for (int j = 0; j < 4; j++)
        t[ty + j*8][tx] = in[((size_t)(b * SS + s0 + ty + j*8)) * 512 + h * 64 + d0 + tx];
    __syncthreads();
#pragma unroll
    for (int j = 0; j < 4; j++) {
        int d = d0 + ty + j*8;
        o[((size_t)bh * 64 + d) * SS + s0 + tx] = __float2half_rn(t[tx][ty + j*8]);
    }
}
__global__ void __launch_bounds__(256) cvt_whead(const float* __restrict__ in, hf* o) {
    __shared__ float t[32][33];
    int k0 = blockIdx.x * 32, d0 = blockIdx.y * 32, h = blockIdx.z;
    int tx = threadIdx.x, ty = threadIdx.y;
#pragma unroll
    for (int j = 0; j < 4; j++)
        t[ty + j*8][tx] = in[(size_t)h * 32768 + (size_t)(k0 + ty + j*8) * 64 + d0 + tx];
    __syncthreads();
#pragma unroll
    for (int j = 0; j < 4; j++) {
        int d = d0 + ty + j*8;
        o[((size_t)(h * 64 + d)) * 512 + k0 + tx] = __float2half_rn(t[tx][ty + j*8]);
    }
}

// ---------------- LayerNorm --------------------------------------------------
__global__ void __launch_bounds__(256) ln_partial_kernel(const float* __restrict__ X) {
    int b = blockIdx.x >> 8, c = blockIdx.x & 255, tid = threadIdx.x;
    const float* p = X + (size_t)b * SD + (size_t)c * 2048;
    float s = 0.f, s2 = 0.f;
#pragma unroll
    for (int i = 0; i < 8; i++) { float v = p[tid + i*256]; s += v; s2 += v*v; }
    __shared__ float sh[256], sh2[256];
    sh[tid] = s; sh2[tid] = s2; __syncthreads();
    for (int o = 128; o; o >>= 1) {
        if (tid < o) { sh[tid] += sh[tid+o]; sh2[tid] += sh2[tid+o]; }
        __syncthreads();
    }
    if (tid == 0) { g_psum[blockIdx.x] = sh[0]; g_psumsq[blockIdx.x] = sh2[0]; }
}
__global__ void __launch_bounds__(256) ln_final_kernel() {
    int b = blockIdx.x, tid = threadIdx.x;
    __shared__ float sh[256], sh2[256];
    sh[tid] = g_psum[b*256 + tid]; sh2[tid] = g_psumsq[b*256 + tid];
    __syncthreads();
    for (int o = 128; o; o >>= 1) {
        if (tid < o) { sh[tid] += sh[tid+o]; sh2[tid] += sh2[tid+o]; }
        __syncthreads();
    }
    if (tid == 0) {
        float mean = sh[0] / (float)SD;
        float var = sh2[0] / (float)SD - mean * mean;
        g_mr[2*b] = mean; g_mr[2*b+1] = rsqrtf(var + 1e-6f);
    }
}
__global__ void __launch_bounds__(256) ln_apply_cvt(
    const float* __restrict__ X, const float* __restrict__ w,
    const float* __restrict__ bb, float* __restrict__ Y, hf* oh)
{
    size_t base = ((size_t)blockIdx.x * 256 + threadIdx.x) * 4;
    int b = (int)(base / SD); size_t sd = base % SD;
    float mean = g_mr[2*b], rstd = g_mr[2*b+1];
    float4 xv = *(const float4*)(X + base);
    float4 wv = *(const float4*)(w + sd);
    float4 bv = *(const float4*)(bb + sd);
    float4 yv;
    yv.x = (xv.x-mean)*rstd*wv.x + bv.x; yv.y = (xv.y-mean)*rstd*wv.y + bv.y;
    yv.z = (xv.z-mean)*rstd*wv.z + bv.z; yv.w = (xv.w-mean)*rstd*wv.w + bv.w;
    *(float4*)(Y + base) = yv;
    st4h(oh, base, yv.x, yv.y, yv.z, yv.w);
}

// ---------------- host driver ------------------------------------------------
#define SMG 32768

struct P {
    float *v, *res, *x1, *x2, *S;
    hf *a, *b, *q, *k, *vt, *ff;
};

static void run_ln(const float* X, const float* w, const float* b, float* Y, hf* oh) {
    ln_partial_kernel<<<BB*256, 256>>>(X);
    ln_final_kernel<<<BB, 256>>>();
    ln_apply_cvt<<<4096, 256>>>(X, w, b, Y, oh);
}

// q input fp16 already in p.a on entry
static void mha_stage(P& p, bool kv_from_y, const float* y,
    const float* wq, const float* bq, const float* wk, const float* bk,
    const float* wv, const float* bv, const float* wo, const float* bo,
    const int* mask, const float* resid, float* outres)
{
    dim3 gP(4, 64), gW(16, 2, 8), bW(32, 8), gVT(32, 2, 64);
    cvt_whead<<<gW, bW>>>(wq, p.b);
    mma_gemm<128,4><<<gP, 256, SMG>>>(p.a, p.b, bq, nullptr, nullptr,
        512, 512, 0,0,0,0,0, p.q);
    if (kv_from_y) cvt_flat<<<4096, 256>>>(y, p.a);
    cvt_whead<<<gW, bW>>>(wk, p.b);
    mma_gemm<128,4><<<gP, 256, SMG>>>(p.a, p.b, bk, nullptr, nullptr,
        512, 512, 0,0,0,0,0, p.k);
    cvt_whead<<<gW, bW>>>(wv, p.b);
    mma_gemm<128,0><<<gP, 256, SMG>>>(p.a, p.b, bv, nullptr, p.v,
        512, 512, 0,0,0,0,0, nullptr);
    cvt_vt<<<gVT, bW>>>(p.v, p.vt);

    // S = Q K^T (batched over bh)
    mma_gemm<128,3><<<dim3(8,8,64), 256, SMG>>>(p.q, p.k, nullptr, nullptr,
        p.S, 64, 1024, 65536, 65536, 1048576, 0, 0, nullptr);
    // fused mask+softmax+PV -> fp16 att output in p.a
    pv_softmax<<<dim3(8, 64), 256, PVSM>>>(p.S, p.vt, mask, p.a);

    cvt_flat<<<256, 256>>>(wo, p.b);
    mma_gemm<128,1><<<gP, 256, SMG>>>(p.a, p.b, bo, resid, outres,
        512, 512, 0,0,0,0,0, nullptr);
}

extern "C" void kernel_launch(void* const* d_in, const int* in_sizes, int n_in,
                              void* d_out, int out_size)
{
#define FP(i) ((const float*)d_in[i])
    const int* src_mask = (const int*)d_in[2];
    const int* trg_mask = (const int*)d_in[3];
    float* out = (float*)d_out;

    cudaFuncSetAttribute(pv_softmax, cudaFuncAttributeMaxDynamicSharedMemorySize, PVSM);

    P p;
    cudaGetSymbolAddress((void**)&p.v,  g_v);  cudaGetSymbolAddress((void**)&p.res, g_res);
    cudaGetSymbolAddress((void**)&p.x1, g_x1); cudaGetSymbolAddress((void**)&p.x2,  g_x2);
    cudaGetSymbolAddress((void**)&p.S,  g_S);
    cudaGetSymbolAddress((void**)&p.a,  g_a);  cudaGetSymbolAddress((void**)&p.b,   g_b);
    cudaGetSymbolAddress((void**)&p.q,  g_q);  cudaGetSymbolAddress((void**)&p.k,   g_k);
    cudaGetSymbolAddress((void**)&p.vt, g_vt); cudaGetSymbolAddress((void**)&p.ff,  g_ff);

    // ---- stage 1: self-attention ----
    cvt_flat<<<4096, 256>>>(FP(0), p.a);
    mha_stage(p, false, nullptr, FP(4), FP(5), FP(6), FP(7), FP(8), FP(9), FP(10), FP(11),
              trg_mask, FP(0), p.res);
    run_ln(p.res, FP(24), FP(25), p.x1, p.a);

    // ---- stage 2: cross-attention ----
    mha_stage(p, true, FP(1), FP(12), FP(13), FP(14), FP(15), FP(16), FP(17), FP(18), FP(19),
              src_mask, p.x1, p.res);
    run_ln(p.res, FP(26), FP(27), p.x2, p.a);

    // ---- stage 3: FFN ----
    cvt_flat<<<1024, 256>>>(FP(20), p.b);
    mma_gemm<128,5><<<dim3(16, 64), 256, SMG>>>(p.a, p.b, FP(21), nullptr,
        nullptr, 512, 2048, 0,0,0,0,0, p.ff);
    cvt_flat<<<1024, 256>>>(FP(22), p.b);
    mma_gemm<128,1><<<dim3(4, 64), 256, SMG>>>(p.ff, p.b, FP(23), p.x2,
        p.res, 2048, 512, 0,0,0,0,0, nullptr);
    run_ln(p.res, FP(28), FP(29), out, p.a);
}